// round 5
// baseline (speedup 1.0000x reference)
#include <cuda_runtime.h>
#include <cuda_fp16.h>
#include <math.h>

#define R 256
#define F4 32           // 128 features = 32 float4
#define NPIX (R * R)

// Static device scratch
__device__ uint2 g_tmph[5 * (size_t)NPIX * F4];  // row-blurred levels, fp16x4 (84 MB)
__device__ uint4 g_Hh[(size_t)NPIX * 16];        // H = G@W1+b1, fp16 (16.8 MB)
__device__ uint2 g_W1p[64 * 128];                // W1 tf32 B-fragments (64 KB)

// ---------------------------------------------------------------------------
// Compile-time gaussian weights -> FFMA-immediate taps
// ---------------------------------------------------------------------------
constexpr double cexp_d(double x) {   // x in (-1, 0]
    double r = x; int k = 0;
    while (r < -0.34657359027997264) { r += 0.69314718055994530942; k++; }
    double term = 1.0, sum = 1.0;
    for (int i = 1; i < 22; i++) { term *= r / (double)i; sum += term; }
    for (int i = 0; i < k; i++) sum *= 0.5;
    return sum;
}

template <int S> struct GWt {
    float w[S];
    constexpr GWt() : w{} {
        double t[S] = {};
        double sum = 0.0;
        for (int n = 0; n < S; n++) {
            double xx = ((double)n - (double)(S - 1) * 0.5) / ((double)S * 0.5);
            t[n] = cexp_d(-0.5 * xx * xx);
            sum += t[n];
        }
        for (int n = 0; n < S; n++) w[n] = (float)(t[n] / sum);
    }
};

__device__ __forceinline__ int reflect_i(int c) {
    c = (c < 0) ? -c : c;
    return (c > R - 1) ? (2 * (R - 1) - c) : c;
}

__device__ __forceinline__ uint2 pack4(float4 v) {
    __half2 a = __floats2half2_rn(v.x, v.y);
    __half2 b = __floats2half2_rn(v.z, v.w);
    uint2 r;
    r.x = *reinterpret_cast<unsigned*>(&a);
    r.y = *reinterpret_cast<unsigned*>(&b);
    return r;
}

__device__ __forceinline__ float4 unpack4(uint2 u) {
    __half2 a = *reinterpret_cast<__half2*>(&u.x);
    __half2 b = *reinterpret_cast<__half2*>(&u.y);
    float2 fa = __half22float2(a);
    float2 fb = __half22float2(b);
    return make_float4(fa.x, fa.y, fb.x, fb.y);
}

__device__ __forceinline__ unsigned f2tf32(float f) {
    unsigned u;
    asm("cvt.rna.tf32.f32 %0, %1;" : "=r"(u) : "f"(f));
    return u;
}

__device__ __forceinline__ void mma_tf32(float* d, unsigned a0, unsigned a1,
                                         unsigned a2, unsigned a3,
                                         unsigned b0, unsigned b1) {
    asm("mma.sync.aligned.m16n8k8.row.col.f32.tf32.tf32.f32 "
        "{%0,%1,%2,%3},{%4,%5,%6,%7},{%8,%9},{%0,%1,%2,%3};"
        : "+f"(d[0]), "+f"(d[1]), "+f"(d[2]), "+f"(d[3])
        : "r"(a0), "r"(a1), "r"(a2), "r"(a3), "r"(b0), "r"(b1));
}

// ---------------------------------------------------------------------------
// W1 -> tf32 B-fragment layout: g_W1p[(kk*4+tig)*128 + n] = {W1[8kk+tig][n],
// W1[8kk+tig+4][n]} as tf32.
// ---------------------------------------------------------------------------
__global__ void k_w1prep(const float* __restrict__ W1) {
    int t = blockIdx.x * 256 + threadIdx.x;   // 8192 total
    int rr = t >> 7;
    int n  = t & 127;
    int kk = rr >> 2, tig = rr & 3;
    uint2 v;
    v.x = f2tf32(W1[(kk * 8 + tig) * 128 + n]);
    v.y = f2tf32(W1[(kk * 8 + tig + 4) * 128 + n]);
    g_W1p[rr * 128 + n] = v;
}

// ---------------------------------------------------------------------------
// Row pass: block = one column j, all 256 rows staged (fp16). 512 threads,
// thread owns 16 rows x 1 float4-slice; 5 levels emitted, reg accumulators.
// ---------------------------------------------------------------------------
template <int S>
__device__ __forceinline__ void row_level(const uint2* __restrict__ stage,
                                          int r0, int f4, int lvl, int j)
{
    constexpr GWt<S> gw{};
    float4 acc[16];
#pragma unroll
    for (int q = 0; q < 16; q++) acc[q] = make_float4(0.f, 0.f, 0.f, 0.f);
#pragma unroll
    for (int r = 0; r < 16 + S - 1; r++) {
        int c = reflect_i(r0 - S / 2 + r);
        float4 v = unpack4(stage[c * 32 + f4]);
#pragma unroll
        for (int q = 0; q < 16; q++) {
            int jj = r - q;
            if (jj >= 0 && jj < S) {
                float k = gw.w[jj];                 // immediate
                acc[q].x += k * v.x; acc[q].y += k * v.y;
                acc[q].z += k * v.z; acc[q].w += k * v.w;
            }
        }
    }
    size_t lb = (size_t)lvl * NPIX * F4;
#pragma unroll
    for (int q = 0; q < 16; q++)
        g_tmph[lb + ((size_t)(r0 + q) * R + j) * F4 + f4] = pack4(acc[q]);
}

__global__ void __launch_bounds__(512, 1) k_rows(const float4* __restrict__ in)
{
    extern __shared__ unsigned char smem_raw[];
    uint2* stage = (uint2*)smem_raw;      // [256][32] fp16x4, 64KB
    int j  = blockIdx.x;
    int t  = threadIdx.x;
    int f4 = t & 31, ig = t >> 5;
    int r0 = ig * 16;

#pragma unroll
    for (int q = 0; q < 16; q++) {
        int row = r0 + q;
        stage[row * 32 + f4] = pack4(in[((size_t)row * R + j) * F4 + f4]);
    }
    __syncthreads();

    row_level<2 >(stage, r0, f4, 0, j);
    row_level<4 >(stage, r0, f4, 1, j);
    row_level<8 >(stage, r0, f4, 2, j);
    row_level<16>(stage, r0, f4, 3, j);
    row_level<32>(stage, r0, f4, 4, j);
}

// ---------------------------------------------------------------------------
// Col pass + H GEMM fused. Block = one row i (256 cols), 512 threads.
// smem: Gacc fp32/tf32 [256][132] = 135168 @ 0
//       stage fp16 [256][32] (65536) / Hs half2 [256][68] (69632) @ 135168
// total 204800
// ---------------------------------------------------------------------------
#define SMEM_CH 204800

template <int S>
__device__ __forceinline__ void col_level(const uint2* __restrict__ stage,
                                          int j0t, int f4, float4* acc)
{
    constexpr GWt<S> gw{};
#pragma unroll
    for (int r = 0; r < 16 + S - 1; r++) {
        int c = reflect_i(j0t - S / 2 + r);
        float4 v = unpack4(stage[c * 32 + f4]);
#pragma unroll
        for (int q = 0; q < 16; q++) {
            int jj = r - q;
            if (jj >= 0 && jj < S) {
                float k = gw.w[jj];                 // immediate
                acc[q].x += k * v.x; acc[q].y += k * v.y;
                acc[q].z += k * v.z; acc[q].w += k * v.w;
            }
        }
    }
}

__global__ void __launch_bounds__(512, 1) k_colsH(const float4* __restrict__ base4,
                                                  const float* __restrict__ b_levels,
                                                  const float* __restrict__ b1)
{
    extern __shared__ unsigned char smem_raw[];
    unsigned* GaccU = (unsigned*)smem_raw;          // [256][132] tf32 at MMA time
    uint2*    stage = (uint2*)(smem_raw + 135168);  // fp16 level row (scaled by bl)

    int i  = blockIdx.x;
    int t  = threadIdx.x;
    int f4 = t & 31, jg = t >> 5;
    int j0t = jg * 16;

    // acc = b0 * base
    float b0 = b_levels[0];
    float4 acc[16];
#pragma unroll
    for (int q = 0; q < 16; q++) {
        float4 v = base4[((size_t)i * R + j0t + q) * F4 + f4];
        acc[q] = make_float4(b0 * v.x, b0 * v.y, b0 * v.z, b0 * v.w);
    }

    // levels 1..5: stage = bl * tmph_row (fp16), then immediate-weight col blur
#pragma unroll
    for (int lvl = 1; lvl <= 5; lvl++) {
        float bl = b_levels[lvl];
        size_t lb = (size_t)(lvl - 1) * NPIX * F4 + (size_t)i * R * F4;
#pragma unroll
        for (int it = 0; it < 16; it++) {
            int idx = it * 512 + t;
            float4 v = unpack4(g_tmph[lb + idx]);
            stage[idx] = pack4(make_float4(bl * v.x, bl * v.y, bl * v.z, bl * v.w));
        }
        __syncthreads();
        switch (lvl) {
            case 1: col_level<2 >(stage, j0t, f4, acc); break;
            case 2: col_level<4 >(stage, j0t, f4, acc); break;
            case 3: col_level<8 >(stage, j0t, f4, acc); break;
            case 4: col_level<16>(stage, j0t, f4, acc); break;
            case 5: col_level<32>(stage, j0t, f4, acc); break;
        }
        __syncthreads();
    }

    // Store G as tf32 into Gacc (stride 132 words; conflict-free for MMA reads)
#pragma unroll
    for (int q = 0; q < 16; q++) {
        uint4 u;
        u.x = f2tf32(acc[q].x); u.y = f2tf32(acc[q].y);
        u.z = f2tf32(acc[q].z); u.w = f2tf32(acc[q].w);
        *reinterpret_cast<uint4*>(&GaccU[(j0t + q) * 132 + 4 * f4]) = u;
    }
    __syncthreads();

    // MMA: 256x128 = 16 m-tiles x 2 n-halves; warp w -> mt = w, loop nh.
    int w    = t >> 5;
    int lane = t & 31;
    int g    = lane >> 2;
    int tig  = lane & 3;
    int mt   = w;

    __half2* Hs2 = (__half2*)stage;   // [256][68]

#pragma unroll
    for (int nh = 0; nh < 2; nh++) {
        float d[8][4];
#pragma unroll
        for (int nt = 0; nt < 8; nt++)
#pragma unroll
            for (int e = 0; e < 4; e++) d[nt][e] = 0.0f;

#pragma unroll 4
        for (int kk = 0; kk < 16; kk++) {
            int arow = (mt * 16 + g) * 132 + kk * 8 + tig;
            unsigned a0 = GaccU[arow];
            unsigned a1 = GaccU[arow + 8 * 132];
            unsigned a2 = GaccU[arow + 4];
            unsigned a3 = GaccU[arow + 8 * 132 + 4];
            int brow = (kk * 4 + tig) * 128 + nh * 64 + g;
#pragma unroll
            for (int nt = 0; nt < 8; nt++) {
                uint2 b = g_W1p[brow + nt * 8];
                mma_tf32(d[nt], a0, a1, a2, a3, b.x, b.y);
            }
        }

        int m0 = mt * 16 + g;
#pragma unroll
        for (int nt = 0; nt < 8; nt++) {
            int n0 = nh * 64 + nt * 8 + 2 * tig;
            float bb0 = b1[n0], bb1 = b1[n0 + 1];
            Hs2[m0 * 68 + (n0 >> 1)]       = __floats2half2_rn(d[nt][0] + bb0,
                                                               d[nt][1] + bb1);
            Hs2[(m0 + 8) * 68 + (n0 >> 1)] = __floats2half2_rn(d[nt][2] + bb0,
                                                               d[nt][3] + bb1);
        }
    }
    __syncthreads();

    // Coalesced fp16 H store: 256 pixels x 16 uint4 (row stride 17 uint4)
    const uint4* Hs4 = (const uint4*)stage;
#pragma unroll
    for (int it = 0; it < 8; it++) {
        int idx = it * 512 + t;
        int p  = idx >> 4;
        int q4 = idx & 15;
        g_Hh[((size_t)i * R + p) * 16 + q4] = Hs4[p * 17 + q4];
    }
}

// ---------------------------------------------------------------------------
// Points: bilerp gather of fp16 H + relu + W2 + b2.
// ---------------------------------------------------------------------------
__global__ void __launch_bounds__(256) k_pts(const float* __restrict__ pt,
                                             const float4* __restrict__ W2v,
                                             const float* __restrict__ b2,
                                             float4* __restrict__ out4)
{
    int t = threadIdx.x, lane = t & 31, w = t >> 5;
    int lh = lane >> 4;
    int lf = lane & 15;

    float4 w2r[8];
#pragma unroll
    for (int j = 0; j < 8; j++) w2r[j] = W2v[lf * 8 + j];
    float b20 = b2[0], b21 = b2[1], b22 = b2[2], b23 = b2[3];

    int p0 = blockIdx.x * 128 + w * 16 + lh;
#pragma unroll 2
    for (int it = 0; it < 8; it++) {
        int p = p0 + it * 2;
        float px = pt[2 * p];
        float py = pt[2 * p + 1];
        float ax = (px + 1.0f) / 2.0f * 255.0f;
        float ay = (py + 1.0f) / 2.0f * 255.0f;
        int ix = (int)ax; if (ix > 255) ix = 255;
        int iy = (int)ay; if (iy > 255) iy = 255;
        float fx = ax - (float)ix;
        float fy = ay - (float)iy;
        int ix1 = (ix + 1 > 255) ? 255 : ix + 1;
        int iy1 = (iy + 1 > 255) ? 255 : iy + 1;
        float w00 = (1.0f - fx) * (1.0f - fy);
        float w01 = (1.0f - fx) * fy;
        float w10 = fx * (1.0f - fy);
        float w11 = fx * fy;

        uint4 c00 = g_Hh[((size_t)(ix  * R + iy )) * 16 + lf];
        uint4 c01 = g_Hh[((size_t)(ix  * R + iy1)) * 16 + lf];
        uint4 c10 = g_Hh[((size_t)(ix1 * R + iy )) * 16 + lf];
        uint4 c11 = g_Hh[((size_t)(ix1 * R + iy1)) * 16 + lf];

        float v[8];
#pragma unroll
        for (int k = 0; k < 8; k++) v[k] = 0.0f;
        {
            const unsigned* cs[4] = {&c00.x, &c01.x, &c10.x, &c11.x};
            float ws[4] = {w00, w01, w10, w11};
#pragma unroll
            for (int cc = 0; cc < 4; cc++) {
                float wgt = ws[cc];
#pragma unroll
                for (int k = 0; k < 4; k++) {
                    __half2 h = *reinterpret_cast<const __half2*>(&cs[cc][k]);
                    float2 f = __half22float2(h);
                    v[2 * k]     += wgt * f.x;
                    v[2 * k + 1] += wgt * f.y;
                }
            }
        }

        float4 o = make_float4(0.f, 0.f, 0.f, 0.f);
#pragma unroll
        for (int j = 0; j < 8; j++) {
            float h = fmaxf(v[j], 0.0f);
            o.x += h * w2r[j].x; o.y += h * w2r[j].y;
            o.z += h * w2r[j].z; o.w += h * w2r[j].w;
        }

#pragma unroll
        for (int off = 8; off; off >>= 1) {
            o.x += __shfl_xor_sync(0xffffffffu, o.x, off);
            o.y += __shfl_xor_sync(0xffffffffu, o.y, off);
            o.z += __shfl_xor_sync(0xffffffffu, o.z, off);
            o.w += __shfl_xor_sync(0xffffffffu, o.w, off);
        }
        if (lf == 0)
            out4[p] = make_float4(o.x + b20, o.y + b21, o.z + b22, o.w + b23);
    }
}

// ---------------------------------------------------------------------------
extern "C" void kernel_launch(void* const* d_in, const int* in_sizes, int n_in,
                              void* d_out, int out_size) {
    const float*  pt       = (const float*)d_in[0];
    const float4* base4    = (const float4*)d_in[1];
    const float*  b_levels = (const float*)d_in[2];
    const float*  W1       = (const float*)d_in[3];
    const float*  b1       = (const float*)d_in[4];
    const float*  W2       = (const float*)d_in[5];
    const float*  b2       = (const float*)d_in[6];
    float* out             = (float*)d_out;

    cudaFuncSetAttribute(k_rows, cudaFuncAttributeMaxDynamicSharedMemorySize, 65536);
    cudaFuncSetAttribute(k_colsH, cudaFuncAttributeMaxDynamicSharedMemorySize,
                         SMEM_CH);

    k_w1prep<<<32, 256>>>(W1);
    k_rows<<<256, 512, 65536>>>(base4);
    k_colsH<<<256, 512, SMEM_CH>>>(base4, b_levels, b1);
    k_pts<<<2048, 256>>>(pt, (const float4*)W2, b2, (float4*)out);
}